// round 14
// baseline (speedup 1.0000x reference)
#include <cuda_runtime.h>
#include <cuda_fp16.h>
#include <cstdint>

// ======================= problem sizes =======================
#define D_IN   4096
#define D_OUT  4096
#define M_TOT  8192
#define MT     128             // tile M
#define NT     128             // tile N
#define KC     64              // K chunk: 64 fp16 = 128B rows (SW128)
#define STAGES 3
#define KITERS (D_IN / KC)     // 64
#define NTHREADS 128           // 4 warps, warp tile 64x64, 2 CTAs/SM
#define NTILES  ((M_TOT / MT) * (D_OUT / NT))   // 64 * 32 = 2048
#define PERSIST 304            // 152 SMs x 2 CTAs

// ======================= scratch =======================
static __device__ __half g_W[(size_t)D_OUT * D_IN];   // 32 MB
static __device__ __half g_X[(size_t)M_TOT * D_IN];   // 64 MB
static __device__ float  g_bias[D_OUT];

__constant__ float NF4_CB[16] = {
  -1.0f, -0.6961928009986877f, -0.5250730514526367f, -0.39491748809814453f,
  -0.28444138169288635f, -0.18477343022823334f, -0.09105003625154495f, 0.0f,
  0.07958029955625534f, 0.16093020141124725f, 0.24611230194568634f,
  0.33791524171829224f, 0.44070982933044434f, 0.5626170039176941f,
  0.6848514676094055f, 1.0f };

// ======================= helpers =======================
__device__ __forceinline__ uint32_t smem_u32(const void* p){
  uint32_t a;
  asm("{ .reg .u64 t; cvta.to.shared.u64 t, %1; cvt.u32.u64 %0, t; }" : "=r"(a) : "l"(p));
  return a;
}
__device__ __forceinline__ uint32_t pack_h2(float a, float b){
  __half2 h = __floats2half2_rn(a, b);
  return *reinterpret_cast<uint32_t*>(&h);
}
__device__ __forceinline__ void cp16(uint32_t s, const void* g){
  asm volatile("cp.async.cg.shared.global [%0], [%1], 16;" :: "r"(s), "l"(g) : "memory");
}
__device__ __forceinline__ void ldsm_x4(uint32_t* r, uint32_t addr){
  asm volatile("ldmatrix.sync.aligned.m8n8.x4.shared.b16 {%0,%1,%2,%3}, [%4];"
               : "=r"(r[0]), "=r"(r[1]), "=r"(r[2]), "=r"(r[3]) : "r"(addr));
}
__device__ __forceinline__ void mma16816(float* c, const uint32_t* a, const uint32_t* b){
  asm volatile("mma.sync.aligned.m16n8k16.row.col.f32.f16.f16.f32 "
               "{%0,%1,%2,%3}, {%4,%5,%6,%7}, {%8,%9}, {%0,%1,%2,%3};"
               : "+f"(c[0]), "+f"(c[1]), "+f"(c[2]), "+f"(c[3])
               : "r"(a[0]), "r"(a[1]), "r"(a[2]), "r"(a[3]), "r"(b[0]), "r"(b[1]));
}

#define MBAR_INIT(addr, cnt) \
  asm volatile("mbarrier.init.shared.b64 [%0], %1;" :: "r"(addr), "r"(cnt) : "memory")

#define MBAR_ARRIVE(addr) \
  asm volatile("mbarrier.arrive.shared.b64 _, [%0];" :: "r"(addr) : "memory")

#define MBAR_WAIT(addr, ph) do {                                               \
  uint32_t _m = (addr), _p = (ph), _d;                                         \
  asm volatile("{\n\t.reg .pred p;\n\t"                                        \
    "mbarrier.try_wait.parity.acquire.cta.shared::cta.b64 p, [%1], %2;\n\t"    \
    "selp.b32 %0, 1, 0, p;\n\t}"                                               \
    : "=r"(_d) : "r"(_m), "r"(_p) : "memory");                                 \
  if (!_d) {                                                                   \
    asm volatile("{\n\t.reg .pred P1;\n"                                       \
      "WL%=:\n\t"                                                              \
      "mbarrier.try_wait.parity.acquire.cta.shared::cta.b64 P1, [%0], %1, 0x989680;\n\t" \
      "@P1 bra.uni WD%=;\n\t"                                                  \
      "bra.uni WL%=;\n"                                                        \
      "WD%=:\n\t}" :: "r"(_m), "r"(_p) : "memory");                            \
  }                                                                            \
} while (0)

// ======================= fused prep kernel (16 elems/thread) ==============
#define WBLK ((int)(((size_t)D_OUT * D_IN / 16) / 256))   // 4096
#define XBLK ((int)(((size_t)M_TOT * D_IN / 16) / 256))   // 8192
#define BBLK (D_OUT / 256)                                // 16

__global__ void k_prep(const float* __restrict__ x,
                       const int* __restrict__ wc, const float* __restrict__ wa,
                       const int* __restrict__ bc, const float* __restrict__ ba){
  __shared__ float lut[16];
  if (threadIdx.x < 16) lut[threadIdx.x] = NF4_CB[threadIdx.x];
  __syncthreads();
  int b = blockIdx.x;
  if (b < WBLK){
    size_t i = ((size_t)b * 256 + threadIdx.x) * 16;
    #pragma unroll
    for (int h = 0; h < 2; ++h){
      size_t j = i + h * 8;
      float am = wa[j >> 6];
      int4 c0 = *reinterpret_cast<const int4*>(wc + j);
      int4 c1 = *reinterpret_cast<const int4*>(wc + j + 4);
      uint4 o;
      o.x = pack_h2(lut[c0.x] * am, lut[c0.y] * am);
      o.y = pack_h2(lut[c0.z] * am, lut[c0.w] * am);
      o.z = pack_h2(lut[c1.x] * am, lut[c1.y] * am);
      o.w = pack_h2(lut[c1.z] * am, lut[c1.w] * am);
      *reinterpret_cast<uint4*>(g_W + j) = o;
    }
  } else if (b < WBLK + XBLK){
    size_t i = ((size_t)(b - WBLK) * 256 + threadIdx.x) * 16;
    #pragma unroll
    for (int h = 0; h < 2; ++h){
      size_t j = i + h * 8;
      float4 a = *reinterpret_cast<const float4*>(x + j);
      float4 c = *reinterpret_cast<const float4*>(x + j + 4);
      uint4 o;
      o.x = pack_h2(a.x, a.y);  o.y = pack_h2(a.z, a.w);
      o.z = pack_h2(c.x, c.y);  o.w = pack_h2(c.z, c.w);
      *reinterpret_cast<uint4*>(g_X + j) = o;
    }
  } else {
    int i = (b - WBLK - XBLK) * 256 + threadIdx.x;
    if (i < D_OUT) g_bias[i] = lut[bc[i]] * ba[i >> 6];
  }
}

// ======================= GEMM (persistent) =======================
#define SOFF_FULL   0
#define SOFF_EMPTY  (SOFF_FULL + STAGES * 8)
#define SOFF_DATA   1024
#define A_BYTES     (MT * KC * 2)            // 16 KB
#define STAGE_BYTES ((MT + NT) * KC * 2)     // 32 KB
#define SMEM_BYTES  (SOFF_DATA + STAGES * STAGE_BYTES)   // 99328 -> 2 CTAs/SM

__device__ __forceinline__ void load_stage(uint32_t base, int kt,
                                           const __half* gA, const __half* gB){
  int t = threadIdx.x;
  #pragma unroll
  for (int i = 0; i < 8; ++i){                 // A: 128 rows x 8 chunks
    int ci  = t + i * NTHREADS;
    int row = ci >> 3, c = ci & 7;
    uint32_t sw = (uint32_t)((c ^ (row & 7)) << 4);
    cp16(base + (uint32_t)(row * 128) + sw,
         gA + (size_t)row * D_IN + kt * KC + c * 8);
  }
  #pragma unroll
  for (int i = 0; i < 8; ++i){                 // B: 128 rows x 8 chunks
    int ci  = t + i * NTHREADS;
    int row = ci >> 3, c = ci & 7;
    uint32_t sw = (uint32_t)((c ^ (row & 7)) << 4);
    cp16(base + A_BYTES + (uint32_t)(row * 128) + sw,
         gB + (size_t)row * D_IN + kt * KC + c * 8);
  }
}

// produce chunk with flattened index pg (this CTA's private sequence)
__device__ __forceinline__ void produce(uint32_t sb, int ps, int pg, int bid){
  int tile = bid + (pg >> 6) * PERSIST;        // global tile id
  int kt   = pg & (KITERS - 1);
  const __half* gA = g_X + ((size_t)(tile >> 5) * MT) * D_IN;   // m-tile
  const __half* gB = g_W + ((size_t)(tile & 31) * NT) * D_IN;   // n-tile
  load_stage(sb + SOFF_DATA + (uint32_t)ps * STAGE_BYTES, kt, gA, gB);
}

__global__ void __launch_bounds__(NTHREADS, 2)
k_gemm(float* __restrict__ out){
  extern __shared__ char smem[];
  uint32_t sb = smem_u32(smem);
  const int tid = threadIdx.x;
  const int wid = tid >> 5;
  const int l   = tid & 31;
  const int bid = blockIdx.x;

  if (tid == 0){
    #pragma unroll
    for (int s = 0; s < STAGES; ++s){
      MBAR_INIT(sb + SOFF_FULL  + s * 8, NTHREADS);  // 128 cp-arrives
      MBAR_INIT(sb + SOFF_EMPTY + s * 8, 4);         // 1 arrive per warp
    }
  }
  __syncthreads();   // only block-wide barrier in the kernel

  const int ntc = (NTILES - bid + PERSIST - 1) / PERSIST;   // tiles for this CTA
  const int nch = ntc << 6;                                 // chunks total

  // warp layout: 2 (m) x 2 (n); warp tile 64(m) x 64(n)
  const int wm = (wid & 1) * 64;
  const int wn = (wid >> 1) * 64;

  // ldmatrix lane addressing
  const int rA   = wm + (l & 15);
  const int hiA  = l >> 4;
  const int r7A  = rA & 7;
  const int rB   = wn + ((l & 16) >> 1) + (l & 7);
  const int hiB  = (l >> 3) & 1;
  const int r7B  = rB & 7;

  float acc[4][8][4];
  #pragma unroll
  for (int f = 0; f < 4; ++f)
    #pragma unroll
    for (int j = 0; j < 8; ++j)
      #pragma unroll
      for (int q = 0; q < 4; ++q) acc[f][j][q] = 0.f;

  // cursors: producer phase starts 1 (fresh-barrier parity trick)
  int ps = 0, pp = 1;
  int cs = 0, cp = 0;
  int pg = 0;

  // prologue: fill 2 stages (never drains again until the very end)
  #pragma unroll
  for (int s = 0; s < STAGES - 1; ++s){
    MBAR_WAIT(sb + SOFF_EMPTY + ps * 8, pp);
    produce(sb, ps, pg, bid);  ++pg;
    asm volatile("cp.async.mbarrier.arrive.noinc.shared::cta.b64 [%0];"
                 :: "r"(sb + SOFF_FULL + ps * 8) : "memory");
    if (++ps == STAGES){ ps = 0; pp ^= 1; }
  }

  for (int cg = 0; cg < nch; ++cg){
    // produce ahead (pipeline runs across tile boundaries)
    if (pg < nch){
      MBAR_WAIT(sb + SOFF_EMPTY + ps * 8, pp);
      produce(sb, ps, pg, bid);  ++pg;
      asm volatile("cp.async.mbarrier.arrive.noinc.shared::cta.b64 [%0];"
                   :: "r"(sb + SOFF_FULL + ps * 8) : "memory");
      if (++ps == STAGES){ ps = 0; pp ^= 1; }
    }

    // consume
    MBAR_WAIT(sb + SOFF_FULL + cs * 8, cp);
    uint32_t As = sb + SOFF_DATA + (uint32_t)cs * STAGE_BYTES;
    uint32_t Bs = As + A_BYTES;
    uint32_t baseA = As + (uint32_t)(rA * 128);
    uint32_t baseB = Bs + (uint32_t)(rB * 128);

    #pragma unroll
    for (int ks = 0; ks < 4; ++ks){
      uint32_t csA = (uint32_t)(((2 * ks + hiA) ^ r7A) << 4);
      uint32_t csB = (uint32_t)(((2 * ks + hiB) ^ r7B) << 4);
      uint32_t a[4][4], b[4][4];
      #pragma unroll
      for (int f = 0; f < 4; ++f)
        ldsm_x4(a[f], baseA + (uint32_t)(f * 2048) + csA);
      #pragma unroll
      for (int nf = 0; nf < 4; ++nf)
        ldsm_x4(b[nf], baseB + (uint32_t)(nf * 2048) + csB);
      #pragma unroll
      for (int nf = 0; nf < 4; ++nf)
        #pragma unroll
        for (int f = 0; f < 4; ++f){
          mma16816(acc[f][2 * nf + 0], a[f], b[nf] + 0);
          mma16816(acc[f][2 * nf + 1], a[f], b[nf] + 2);
        }
    }

    __syncwarp();
    if (l == 0) MBAR_ARRIVE(sb + SOFF_EMPTY + cs * 8);
    if (++cs == STAGES){ cs = 0; cp ^= 1; }

    // tile finished -> epilogue (next tile's loads already in flight)
    if ((cg & (KITERS - 1)) == (KITERS - 1)){
      int tile = bid + (cg >> 6) * PERSIST;
      int m0g = (tile >> 5) * MT;
      int n0g = (tile & 31) * NT;
      const int gid = l >> 2, tig = l & 3;
      const int colbase = n0g + wn + 2 * tig;
      #pragma unroll
      for (int f = 0; f < 4; ++f){
        int row0 = m0g + wm + 16 * f + gid;
        float* o0 = out + (size_t)row0 * D_OUT;
        float* o1 = o0 + (size_t)8 * D_OUT;
        #pragma unroll
        for (int j = 0; j < 8; ++j){
          int cg2 = colbase + 8 * j;
          float b0 = g_bias[cg2], b1 = g_bias[cg2 + 1];
          float2 v0 = { acc[f][j][0] + b0, acc[f][j][1] + b1 };
          float2 v1 = { acc[f][j][2] + b0, acc[f][j][3] + b1 };
          *reinterpret_cast<float2*>(o0 + cg2) = v0;
          *reinterpret_cast<float2*>(o1 + cg2) = v1;
        }
      }
      #pragma unroll
      for (int f = 0; f < 4; ++f)
        #pragma unroll
        for (int j = 0; j < 8; ++j)
          #pragma unroll
          for (int q = 0; q < 4; ++q) acc[f][j][q] = 0.f;
    }
  }
}

// ======================= launch =======================
extern "C" void kernel_launch(void* const* d_in, const int* in_sizes, int n_in,
                              void* d_out, int out_size){
  const float* x  = (const float*)d_in[0];
  const int*   wc = (const int*)  d_in[1];
  const float* wa = (const float*)d_in[2];
  const int*   bc = (const int*)  d_in[3];
  const float* ba = (const float*)d_in[4];
  float* out = (float*)d_out;

  cudaFuncSetAttribute(k_gemm, cudaFuncAttributeMaxDynamicSharedMemorySize, SMEM_BYTES);

  k_prep<<<WBLK + XBLK + BBLK, 256>>>(x, wc, wa, bc, ba);

  k_gemm<<<PERSIST, NTHREADS, SMEM_BYTES>>>(out);
}

// round 15
// speedup vs baseline: 1.0533x; 1.0533x over previous
#include <cuda_runtime.h>
#include <cuda_fp16.h>
#include <cstdint>

// ======================= problem sizes =======================
#define D_IN   4096
#define D_OUT  4096
#define M_TOT  8192
#define MT     128             // CTA M tile
#define NT     128             // CTA N tile
#define KC     64              // K chunk: 64 fp16 = 128B rows (SW128)
#define STAGES 3
#define KITERS (D_IN / KC)     // 64
#define NTHREADS 128           // 4 warps, warp tile 64x64, 2 CTAs/SM

// ======================= scratch =======================
static __device__ __half g_W[(size_t)D_OUT * D_IN];   // 32 MB
static __device__ __half g_X[(size_t)M_TOT * D_IN];   // 64 MB
static __device__ float  g_bias[D_OUT];

__constant__ float NF4_CB[16] = {
  -1.0f, -0.6961928009986877f, -0.5250730514526367f, -0.39491748809814453f,
  -0.28444138169288635f, -0.18477343022823334f, -0.09105003625154495f, 0.0f,
  0.07958029955625534f, 0.16093020141124725f, 0.24611230194568634f,
  0.33791524171829224f, 0.44070982933044434f, 0.5626170039176941f,
  0.6848514676094055f, 1.0f };

// ======================= helpers =======================
__device__ __forceinline__ uint32_t smem_u32(const void* p){
  uint32_t a;
  asm("{ .reg .u64 t; cvta.to.shared.u64 t, %1; cvt.u32.u64 %0, t; }" : "=r"(a) : "l"(p));
  return a;
}
__device__ __forceinline__ uint32_t pack_h2(float a, float b){
  __half2 h = __floats2half2_rn(a, b);
  return *reinterpret_cast<uint32_t*>(&h);
}
__device__ __forceinline__ void cp16(uint32_t s, const void* g){
  asm volatile("cp.async.cg.shared.global [%0], [%1], 16;" :: "r"(s), "l"(g) : "memory");
}
__device__ __forceinline__ void ldsm_x4(uint32_t* r, uint32_t addr){
  asm volatile("ldmatrix.sync.aligned.m8n8.x4.shared.b16 {%0,%1,%2,%3}, [%4];"
               : "=r"(r[0]), "=r"(r[1]), "=r"(r[2]), "=r"(r[3]) : "r"(addr));
}
__device__ __forceinline__ void mma16816(float* c, const uint32_t* a, const uint32_t* b){
  asm volatile("mma.sync.aligned.m16n8k16.row.col.f32.f16.f16.f32 "
               "{%0,%1,%2,%3}, {%4,%5,%6,%7}, {%8,%9}, {%0,%1,%2,%3};"
               : "+f"(c[0]), "+f"(c[1]), "+f"(c[2]), "+f"(c[3])
               : "r"(a[0]), "r"(a[1]), "r"(a[2]), "r"(a[3]), "r"(b[0]), "r"(b[1]));
}
__device__ __forceinline__ void stg_cs_v2(float* p, float x, float y){
  asm volatile("st.global.cs.v2.f32 [%0], {%1, %2};" :: "l"(p), "f"(x), "f"(y) : "memory");
}

#define MBAR_INIT(addr, cnt) \
  asm volatile("mbarrier.init.shared.b64 [%0], %1;" :: "r"(addr), "r"(cnt) : "memory")

#define MBAR_ARRIVE(addr) \
  asm volatile("mbarrier.arrive.shared.b64 _, [%0];" :: "r"(addr) : "memory")

#define MBAR_WAIT(addr, ph) do {                                               \
  uint32_t _m = (addr), _p = (ph), _d;                                         \
  asm volatile("{\n\t.reg .pred p;\n\t"                                        \
    "mbarrier.try_wait.parity.acquire.cta.shared::cta.b64 p, [%1], %2;\n\t"    \
    "selp.b32 %0, 1, 0, p;\n\t}"                                               \
    : "=r"(_d) : "r"(_m), "r"(_p) : "memory");                                 \
  if (!_d) {                                                                   \
    asm volatile("{\n\t.reg .pred P1;\n"                                       \
      "WL%=:\n\t"                                                              \
      "mbarrier.try_wait.parity.acquire.cta.shared::cta.b64 P1, [%0], %1, 0x989680;\n\t" \
      "@P1 bra.uni WD%=;\n\t"                                                  \
      "bra.uni WL%=;\n"                                                        \
      "WD%=:\n\t}" :: "r"(_m), "r"(_p) : "memory");                            \
  }                                                                            \
} while (0)

// ======================= fused prep kernel (512 thr, 16 elems/thread) =====
#define PTHREADS 512
#define WBLK ((int)(((size_t)D_OUT * D_IN / 16) / PTHREADS))   // 2048
#define XBLK ((int)(((size_t)M_TOT * D_IN / 16) / PTHREADS))   // 4096
#define BBLK (D_OUT / PTHREADS)                                // 8

__global__ void k_prep(const float* __restrict__ x,
                       const int* __restrict__ wc, const float* __restrict__ wa,
                       const int* __restrict__ bc, const float* __restrict__ ba){
  __shared__ float lut[16];
  if (threadIdx.x < 16) lut[threadIdx.x] = NF4_CB[threadIdx.x];
  __syncthreads();
  int b = blockIdx.x;
  if (b < WBLK){
    size_t i = ((size_t)b * PTHREADS + threadIdx.x) * 16;
    #pragma unroll
    for (int h = 0; h < 2; ++h){
      size_t j = i + h * 8;
      float am = wa[j >> 6];
      int4 c0 = *reinterpret_cast<const int4*>(wc + j);
      int4 c1 = *reinterpret_cast<const int4*>(wc + j + 4);
      uint4 o;
      o.x = pack_h2(lut[c0.x] * am, lut[c0.y] * am);
      o.y = pack_h2(lut[c0.z] * am, lut[c0.w] * am);
      o.z = pack_h2(lut[c1.x] * am, lut[c1.y] * am);
      o.w = pack_h2(lut[c1.z] * am, lut[c1.w] * am);
      *reinterpret_cast<uint4*>(g_W + j) = o;
    }
  } else if (b < WBLK + XBLK){
    size_t i = ((size_t)(b - WBLK) * PTHREADS + threadIdx.x) * 16;
    #pragma unroll
    for (int h = 0; h < 2; ++h){
      size_t j = i + h * 8;
      float4 a = *reinterpret_cast<const float4*>(x + j);
      float4 c = *reinterpret_cast<const float4*>(x + j + 4);
      uint4 o;
      o.x = pack_h2(a.x, a.y);  o.y = pack_h2(a.z, a.w);
      o.z = pack_h2(c.x, c.y);  o.w = pack_h2(c.z, c.w);
      *reinterpret_cast<uint4*>(g_X + j) = o;
    }
  } else {
    int i = (b - WBLK - XBLK) * PTHREADS + threadIdx.x;
    if (i < D_OUT) g_bias[i] = lut[bc[i]] * ba[i >> 6];
  }
}

// ======================= GEMM =======================
// SMEM: mbarriers at 0..47, bias cache at 512..1023, data stages at 1024.
#define SOFF_FULL   0
#define SOFF_EMPTY  (SOFF_FULL + STAGES * 8)
#define SOFF_BIAS   512
#define SOFF_DATA   1024
#define A_BYTES     (MT * KC * 2)            // 16 KB
#define STAGE_BYTES ((MT + NT) * KC * 2)     // 32 KB
#define SMEM_BYTES  (SOFF_DATA + STAGES * STAGE_BYTES)   // 99328 -> 2 CTAs/SM

__device__ __forceinline__ void load_stage(uint32_t base, int kt,
                                           const __half* gA, const __half* gB){
  int t = threadIdx.x;
  #pragma unroll
  for (int i = 0; i < 8; ++i){                 // A: 128 rows x 8 chunks
    int ci  = t + i * NTHREADS;
    int row = ci >> 3, c = ci & 7;
    uint32_t sw = (uint32_t)((c ^ (row & 7)) << 4);
    cp16(base + (uint32_t)(row * 128) + sw,
         gA + (size_t)row * D_IN + kt * KC + c * 8);
  }
  #pragma unroll
  for (int i = 0; i < 8; ++i){                 // B: 128 rows x 8 chunks
    int ci  = t + i * NTHREADS;
    int row = ci >> 3, c = ci & 7;
    uint32_t sw = (uint32_t)((c ^ (row & 7)) << 4);
    cp16(base + A_BYTES + (uint32_t)(row * 128) + sw,
         gB + (size_t)row * D_IN + kt * KC + c * 8);
  }
}

__global__ void __launch_bounds__(NTHREADS, 2)
k_gemm(float* __restrict__ out){
  extern __shared__ char smem[];
  uint32_t sb = smem_u32(smem);
  const int tid = threadIdx.x;
  const int wid = tid >> 5;
  const int l   = tid & 31;

  const int m0g = blockIdx.y * MT;
  const int n0g = blockIdx.x * NT;

  if (tid == 0){
    #pragma unroll
    for (int s = 0; s < STAGES; ++s){
      MBAR_INIT(sb + SOFF_FULL  + s * 8, NTHREADS);  // 128 cp-arrives
      MBAR_INIT(sb + SOFF_EMPTY + s * 8, 4);         // 1 arrive per warp
    }
  }
  // cache this CTA's 128 bias values in smem (g_bias ready: prep precedes)
  reinterpret_cast<float*>(smem + SOFF_BIAS)[tid] = g_bias[n0g + tid];
  __syncthreads();   // only block-wide barrier in the kernel

  const __half* gA = g_X + (size_t)m0g * D_IN;
  const __half* gB = g_W + (size_t)n0g * D_IN;

  // warp layout: 2 (m) x 2 (n); warp tile 64(m) x 64(n)
  const int wm = (wid & 1) * 64;
  const int wn = (wid >> 1) * 64;

  // ldmatrix lane addressing
  const int rA   = wm + (l & 15);
  const int hiA  = l >> 4;
  const int r7A  = rA & 7;
  const int rB   = wn + ((l & 16) >> 1) + (l & 7);
  const int hiB  = (l >> 3) & 1;
  const int r7B  = rB & 7;

  float acc[4][8][4];
  #pragma unroll
  for (int f = 0; f < 4; ++f)
    #pragma unroll
    for (int j = 0; j < 8; ++j)
      #pragma unroll
      for (int q = 0; q < 4; ++q) acc[f][j][q] = 0.f;

  // cursors: producer phase starts 1 (fresh-barrier parity trick)
  int ps = 0, pp = 1;
  int cs = 0, cp = 0;

  // prologue: fill stages 0..STAGES-2
  #pragma unroll
  for (int s = 0; s < STAGES - 1; ++s){
    MBAR_WAIT(sb + SOFF_EMPTY + ps * 8, pp);
    load_stage(sb + SOFF_DATA + (uint32_t)ps * STAGE_BYTES, s, gA, gB);
    asm volatile("cp.async.mbarrier.arrive.noinc.shared::cta.b64 [%0];"
                 :: "r"(sb + SOFF_FULL + ps * 8) : "memory");
    if (++ps == STAGES){ ps = 0; pp ^= 1; }
  }

  for (int kt = 0; kt < KITERS; ++kt){
    // produce chunk kt + STAGES - 1
    int kp = kt + STAGES - 1;
    if (kp < KITERS){
      MBAR_WAIT(sb + SOFF_EMPTY + ps * 8, pp);
      load_stage(sb + SOFF_DATA + (uint32_t)ps * STAGE_BYTES, kp, gA, gB);
      asm volatile("cp.async.mbarrier.arrive.noinc.shared::cta.b64 [%0];"
                   :: "r"(sb + SOFF_FULL + ps * 8) : "memory");
      if (++ps == STAGES){ ps = 0; pp ^= 1; }
    }

    // consume chunk kt
    MBAR_WAIT(sb + SOFF_FULL + cs * 8, cp);
    uint32_t As = sb + SOFF_DATA + (uint32_t)cs * STAGE_BYTES;
    uint32_t Bs = As + A_BYTES;
    uint32_t baseA = As + (uint32_t)(rA * 128);
    uint32_t baseB = Bs + (uint32_t)(rB * 128);

    #pragma unroll
    for (int ks = 0; ks < 4; ++ks){
      uint32_t csA = (uint32_t)(((2 * ks + hiA) ^ r7A) << 4);
      uint32_t csB = (uint32_t)(((2 * ks + hiB) ^ r7B) << 4);
      uint32_t a[4][4], b[4][4];
      #pragma unroll
      for (int f = 0; f < 4; ++f)
        ldsm_x4(a[f], baseA + (uint32_t)(f * 2048) + csA);
      #pragma unroll
      for (int nf = 0; nf < 4; ++nf)
        ldsm_x4(b[nf], baseB + (uint32_t)(nf * 2048) + csB);
      #pragma unroll
      for (int nf = 0; nf < 4; ++nf)
        #pragma unroll
        for (int f = 0; f < 4; ++f){
          mma16816(acc[f][2 * nf + 0], a[f], b[nf] + 0);
          mma16816(acc[f][2 * nf + 1], a[f], b[nf] + 2);
        }
    }

    __syncwarp();
    if (l == 0) MBAR_ARRIVE(sb + SOFF_EMPTY + cs * 8);
    if (++cs == STAGES){ cs = 0; cp ^= 1; }
  }

  // ---------------- epilogue ----------------
  const float* bsm = reinterpret_cast<const float*>(smem + SOFF_BIAS);
  const int gid = l >> 2, tig = l & 3;
  const int colloc = wn + 2 * tig;              // local col within CTA tile
  #pragma unroll
  for (int f = 0; f < 4; ++f){
    int row0 = m0g + wm + 16 * f + gid;
    float* o0 = out + (size_t)row0 * D_OUT + n0g;
    float* o1 = o0 + (size_t)8 * D_OUT;
    #pragma unroll
    for (int j = 0; j < 8; ++j){
      int cl = colloc + 8 * j;
      float b0 = bsm[cl], b1 = bsm[cl + 1];
      stg_cs_v2(o0 + cl, acc[f][j][0] + b0, acc[f][j][1] + b1);
      stg_cs_v2(o1 + cl, acc[f][j][2] + b0, acc[f][j][3] + b1);
    }
  }
}

// ======================= launch =======================
extern "C" void kernel_launch(void* const* d_in, const int* in_sizes, int n_in,
                              void* d_out, int out_size){
  const float* x  = (const float*)d_in[0];
  const int*   wc = (const int*)  d_in[1];
  const float* wa = (const float*)d_in[2];
  const int*   bc = (const int*)  d_in[3];
  const float* ba = (const float*)d_in[4];
  float* out = (float*)d_out;

  cudaFuncSetAttribute(k_gemm, cudaFuncAttributeMaxDynamicSharedMemorySize, SMEM_BYTES);

  k_prep<<<WBLK + XBLK + BBLK, PTHREADS>>>(x, wc, wa, bc, ba);

  dim3 grid(D_OUT / NT, M_TOT / MT);   // (32, 64)
  k_gemm<<<grid, NTHREADS, SMEM_BYTES>>>(out);
}